// round 6
// baseline (speedup 1.0000x reference)
#include <cuda_runtime.h>

// GatedGCN: 4 layers of  e' = e + relu(Dh[src]+Eh[dst]+Ce);
//                        h' = h + relu(Ah + segsum(Bh[src]*sig(e'))/ (segsum(sig)+eps))
// followed by a 96->48->24->10 MLP + sigmoid.
// All GEMMs use packed fp32x2 FFMA (fma.rn.f32x2). The big per-edge GEMM
// (Ce = e @ Cw) is fused with the gating / atomic aggregation / e-residual.

#define NN   50000
#define EE   800000
#define NDIM 96
#define NCLS 10
#define EPSI 1e-6f

typedef unsigned long long u64;

// persistent device scratch (zero-init at module load; num/den invariantly
// zero at kernel_launch entry and re-zeroed defensively each call)
__device__ float g_h[NN * NDIM];
__device__ float g_e[(size_t)EE * NDIM];
__device__ float g_nbuf[4ull * NN * NDIM];   // slices: 0=Ah 1=Bh 2=Dh 3=Eh
__device__ float g_num[NN * NDIM];
__device__ float g_den[NN * NDIM];

__device__ __forceinline__ u64 pk2(float lo, float hi) {
    u64 r; asm("mov.b64 %0, {%1, %2};" : "=l"(r) : "f"(lo), "f"(hi)); return r;
}
__device__ __forceinline__ void upk2(u64 v, float& lo, float& hi) {
    asm("mov.b64 {%0, %1}, %2;" : "=f"(lo), "=f"(hi) : "l"(v));
}
__device__ __forceinline__ u64 ffma2(u64 a, u64 b, u64 c) {
    u64 d; asm("fma.rn.f32x2 %0, %1, %2, %3;" : "=l"(d) : "l"(a), "l"(b), "l"(c));
    return d;
}
__device__ __forceinline__ float sigmoidf_(float x) {
    return __fdividef(1.f, 1.f + __expf(-x));
}

// ---------------------------------------------------------------------------
// Generic [M,K] x [K,96] + b GEMM, K in {32,96}. blockIdx.y selects one of up
// to four (w,b,out) triples so all 4 node GEMMs of a layer run in one launch.
// Tile: 64 rows x 96 cols per block, 256 threads (16x16), thread tile 4x6
// (3 f32x2 column pairs), K chunked by 32 through SMEM.
// ---------------------------------------------------------------------------
struct GemmSet { const float* w; const float* b; float* out; };

__global__ __launch_bounds__(256) void gemm96_kernel(
        const float* __restrict__ x, int M, int K,
        GemmSet s0, GemmSet s1, GemmSet s2, GemmSet s3) {
    __shared__ __align__(16) float hs[64 * 97];
    __shared__ __align__(16) float ws[32 * 96];
    __shared__ float bs[96];
    const GemmSet s = (blockIdx.y == 0) ? s0 : (blockIdx.y == 1) ? s1
                    : (blockIdx.y == 2) ? s2 : s3;
    const int tid = threadIdx.x;
    const int tx = tid & 15, ty = tid >> 4;
    const int r0 = blockIdx.x * 64;

    for (int idx = tid; idx < 64 * K; idx += 256) {
        int r = idx / K, k = idx - r * K;
        int row = r0 + r;
        hs[r * 97 + k] = (row < M) ? x[row * K + k] : 0.f;
    }
    if (tid < 96) bs[tid] = s.b[tid];

    u64 acc[4][3];
#pragma unroll
    for (int i = 0; i < 4; ++i)
#pragma unroll
        for (int j = 0; j < 3; ++j) acc[i][j] = 0ull;

    const int nchunk = K >> 5;
    for (int c = 0; c < nchunk; ++c) {
        for (int idx = tid; idx < 32 * 96; idx += 256)
            ws[idx] = s.w[c * (32 * 96) + idx];
        __syncthreads();
#pragma unroll 8
        for (int kk = 0; kk < 32; ++kk) {
            u64 wp0 = *(const u64*)&ws[kk * 96 + tx * 6];
            u64 wp1 = *(const u64*)&ws[kk * 96 + tx * 6 + 2];
            u64 wp2 = *(const u64*)&ws[kk * 96 + tx * 6 + 4];
#pragma unroll
            for (int i = 0; i < 4; ++i) {
                float hv = hs[(ty + 16 * i) * 97 + (c << 5) + kk];
                u64 hh = pk2(hv, hv);
                acc[i][0] = ffma2(hh, wp0, acc[i][0]);
                acc[i][1] = ffma2(hh, wp1, acc[i][1]);
                acc[i][2] = ffma2(hh, wp2, acc[i][2]);
            }
        }
        __syncthreads();
    }

#pragma unroll
    for (int i = 0; i < 4; ++i) {
        int row = r0 + ty + 16 * i;
        if (row < M) {
#pragma unroll
            for (int j = 0; j < 3; ++j) {
                int col = tx * 6 + 2 * j;
                float lo, hi; upk2(acc[i][j], lo, hi);
                float2 o; o.x = lo + bs[col]; o.y = hi + bs[col + 1];
                *(float2*)&s.out[row * 96 + col] = o;
            }
        }
    }
}

// ---------------------------------------------------------------------------
// Fused edge kernel: per block of 128 edges
//   Ce = e_tile @ Cw        (register-tiled f32x2 GEMM, e transposed in SMEM)
//   e_new = Ce + Cb + Dh[src] + Eh[dst];  sigma = sigmoid(e_new)
//   atomic num[dst] += Bh[src]*sigma;  den[dst] += sigma
//   e <- e + relu(e_new)    (in place)
// 128 threads (8 tx x 16 ty): thread tile 8 rows x 6 f32x2 col-pairs.
// ---------------------------------------------------------------------------
#define EDGE_SMEM ((96 * 128 + 96 * 96 + 96) * 4 + 2 * 128 * 4)

__global__ __launch_bounds__(128) void edge_kernel(
        const float* __restrict__ Cw, const float* __restrict__ Cb,
        const int* __restrict__ src, const int* __restrict__ dst) {
    extern __shared__ __align__(16) float sm[];
    float* esT  = sm;                    // [96][128]  (k-major, conflict-free)
    float* ws   = sm + 96 * 128;         // [96][96]
    float* cbs  = ws + 96 * 96;          // [96]
    int*   ssrc = (int*)(cbs + 96);      // [128]
    int*   sdst = ssrc + 128;            // [128]

    const int tid = threadIdx.x;
    const int tx = tid & 7, ty = tid >> 3;
    const int e0 = blockIdx.x * 128;
    const int gbase = e0 * 96;

    for (int idx = tid; idx < 128 * 96; idx += 128) {
        int r = idx / 96, k = idx - r * 96;
        esT[k * 128 + r] = g_e[gbase + idx];
    }
    for (int idx = tid; idx < 96 * 96; idx += 128) ws[idx] = Cw[idx];
    if (tid < 96) cbs[tid] = Cb[tid];
    ssrc[tid] = src[e0 + tid];
    sdst[tid] = dst[e0 + tid];
    __syncthreads();

    u64 acc[8][6];
#pragma unroll
    for (int i = 0; i < 8; ++i)
#pragma unroll
        for (int j = 0; j < 6; ++j) acc[i][j] = 0ull;

#pragma unroll 4
    for (int k = 0; k < 96; ++k) {
        u64 wp[6];
#pragma unroll
        for (int j = 0; j < 6; ++j)
            wp[j] = *(const u64*)&ws[k * 96 + tx * 12 + 2 * j];
#pragma unroll
        for (int i = 0; i < 8; ++i) {
            float hv = esT[k * 128 + ty + 16 * i];
            u64 hh = pk2(hv, hv);
#pragma unroll
            for (int j = 0; j < 6; ++j) acc[i][j] = ffma2(hh, wp[j], acc[i][j]);
        }
    }

    const float* __restrict__ Bh = g_nbuf + 1ull * NN * 96;
    const float* __restrict__ Dh = g_nbuf + 2ull * NN * 96;
    const float* __restrict__ Eh = g_nbuf + 3ull * NN * 96;

#pragma unroll
    for (int i = 0; i < 8; ++i) {
        int r = ty + 16 * i;
        int s = ssrc[r] * 96;
        int d = sdst[r] * 96;
        int ebase = (e0 + r) * 96;
#pragma unroll
        for (int j = 0; j < 6; ++j) {
            int col = tx * 12 + 2 * j;
            float lo, hi; upk2(acc[i][j], lo, hi);
            float2 dh = *(const float2*)&Dh[s + col];
            float2 eh = *(const float2*)&Eh[d + col];
            float2 bh = *(const float2*)&Bh[s + col];
            float en0 = lo + cbs[col]     + dh.x + eh.x;
            float en1 = hi + cbs[col + 1] + dh.y + eh.y;
            float sg0 = sigmoidf_(en0);
            float sg1 = sigmoidf_(en1);
            atomicAdd(&g_num[d + col],     bh.x * sg0);
            atomicAdd(&g_num[d + col + 1], bh.y * sg1);
            atomicAdd(&g_den[d + col],     sg0);
            atomicAdd(&g_den[d + col + 1], sg1);
            float2 eo;
            eo.x = esT[col * 128 + r]       + fmaxf(en0, 0.f);
            eo.y = esT[(col + 1) * 128 + r] + fmaxf(en1, 0.f);
            *(float2*)&g_e[ebase + col] = eo;
        }
    }
}

// h <- h + relu(Ah + num/(den+eps));  reset num/den for the next layer/replay
__global__ void node_update_kernel() {
    int i = blockIdx.x * blockDim.x + threadIdx.x;
    if (i < NN * NDIM) {
        float hn = g_nbuf[i] + __fdividef(g_num[i], g_den[i] + EPSI);
        g_h[i] += fmaxf(hn, 0.f);
        g_num[i] = 0.f;
        g_den[i] = 0.f;
    }
}

__global__ void zero_nd_kernel() {
    int i = blockIdx.x * blockDim.x + threadIdx.x;
    if (i < NN * NDIM) { g_num[i] = 0.f; g_den[i] = 0.f; }
}

// ---------------------------------------------------------------------------
// Fused MLP readout + sigmoid: 64 nodes per block, all weights + activations
// staged in SMEM (odd-padded rows -> conflict-free).
// ---------------------------------------------------------------------------
__global__ __launch_bounds__(256) void readout_kernel(
        const float* __restrict__ w0, const float* __restrict__ b0,
        const float* __restrict__ w1, const float* __restrict__ b1,
        const float* __restrict__ w2, const float* __restrict__ b2,
        float* __restrict__ out) {
    __shared__ float w0s[96 * 48];
    __shared__ float w1s[48 * 24];
    __shared__ float w2s[24 * 10];
    __shared__ float b0s[48], b1s[24], b2s[10];
    __shared__ float y0s[64 * 49];
    __shared__ float y1s[64 * 25];

    const int tid = threadIdx.x;
    const int n0 = blockIdx.x * 64;

    for (int idx = tid; idx < 96 * 48; idx += 256) w0s[idx] = w0[idx];
    for (int idx = tid; idx < 48 * 24; idx += 256) w1s[idx] = w1[idx];
    if (tid < 24 * 10) w2s[tid] = w2[tid];
    if (tid < 48) b0s[tid] = b0[tid];
    if (tid < 24) b1s[tid] = b1[tid];
    if (tid < 10) b2s[tid] = b2[tid];
    __syncthreads();

    {   // layer 0: 96 -> 48, relu
        int n = tid & 63, cg = tid >> 6;       // 4 col groups of 12
        int row = n0 + n;
        float a[12];
#pragma unroll
        for (int c = 0; c < 12; ++c) a[c] = b0s[cg * 12 + c];
        if (row < NN) {
            for (int k = 0; k < 96; ++k) {
                float hv = g_h[row * 96 + k];
#pragma unroll
                for (int c = 0; c < 12; ++c) a[c] += hv * w0s[k * 48 + cg * 12 + c];
            }
        }
#pragma unroll
        for (int c = 0; c < 12; ++c) y0s[n * 49 + cg * 12 + c] = fmaxf(a[c], 0.f);
    }
    __syncthreads();
    {   // layer 1: 48 -> 24, relu
        int n = tid & 63, cg = tid >> 6;       // 4 col groups of 6
        float a[6];
#pragma unroll
        for (int c = 0; c < 6; ++c) a[c] = b1s[cg * 6 + c];
        for (int k = 0; k < 48; ++k) {
            float v = y0s[n * 49 + k];
#pragma unroll
            for (int c = 0; c < 6; ++c) a[c] += v * w1s[k * 24 + cg * 6 + c];
        }
#pragma unroll
        for (int c = 0; c < 6; ++c) y1s[n * 25 + cg * 6 + c] = fmaxf(a[c], 0.f);
    }
    __syncthreads();
    // layer 2: 24 -> 10, sigmoid
    for (int idx = tid; idx < 64 * NCLS; idx += 256) {
        int n = idx / NCLS, c = idx - n * NCLS;
        int row = n0 + n;
        if (row < NN) {
            float a = b2s[c];
#pragma unroll
            for (int k = 0; k < 24; ++k) a += y1s[n * 25 + k] * w2s[k * NCLS + c];
            out[row * NCLS + c] = sigmoidf_(a);
        }
    }
}

// ---------------------------------------------------------------------------
extern "C" void kernel_launch(void* const* d_in, const int* in_sizes, int n_in,
                              void* d_out, int out_size) {
    const float* h_in = (const float*)d_in[0];
    const float* e_in = (const float*)d_in[1];
    const int*   src  = (const int*)d_in[2];
    const int*   dst  = (const int*)d_in[3];
    const float* fp_w = (const float*)d_in[4];
    const float* fp_b = (const float*)d_in[5];
    const float* ep_w = (const float*)d_in[6];
    const float* ep_b = (const float*)d_in[7];
    const float* A_w  = (const float*)d_in[8];
    const float* A_b  = (const float*)d_in[9];
    const float* B_w  = (const float*)d_in[10];
    const float* B_b  = (const float*)d_in[11];
    const float* C_w  = (const float*)d_in[12];
    const float* C_b  = (const float*)d_in[13];
    const float* D_w  = (const float*)d_in[14];
    const float* D_b  = (const float*)d_in[15];
    const float* E_w  = (const float*)d_in[16];
    const float* E_b  = (const float*)d_in[17];
    const float* m0w  = (const float*)d_in[18];
    const float* m0b  = (const float*)d_in[19];
    const float* m1w  = (const float*)d_in[20];
    const float* m1b  = (const float*)d_in[21];
    const float* m2w  = (const float*)d_in[22];
    const float* m2b  = (const float*)d_in[23];
    float* out = (float*)d_out;

    float *ph, *pe, *pnb;
    cudaGetSymbolAddress((void**)&ph,  g_h);
    cudaGetSymbolAddress((void**)&pe,  g_e);
    cudaGetSymbolAddress((void**)&pnb, g_nbuf);

    cudaFuncSetAttribute(edge_kernel,
                         cudaFuncAttributeMaxDynamicSharedMemorySize, EDGE_SMEM);

    const int nblk = (NN + 63) / 64;            // 782
    zero_nd_kernel<<<(NN * NDIM + 1023) / 1024, 1024>>>();

    GemmSet sfp{fp_w, fp_b, ph};
    gemm96_kernel<<<dim3(nblk, 1), 256>>>(h_in, NN, 32, sfp, sfp, sfp, sfp);
    GemmSet sep{ep_w, ep_b, pe};
    gemm96_kernel<<<dim3(EE / 64, 1), 256>>>(e_in, EE, 32, sep, sep, sep, sep);

    for (int l = 0; l < 4; ++l) {
        GemmSet sA{A_w + l * 9216, A_b + l * 96, pnb};
        GemmSet sB{B_w + l * 9216, B_b + l * 96, pnb + 1ull * NN * 96};
        GemmSet sD{D_w + l * 9216, D_b + l * 96, pnb + 2ull * NN * 96};
        GemmSet sE{E_w + l * 9216, E_b + l * 96, pnb + 3ull * NN * 96};
        gemm96_kernel<<<dim3(nblk, 4), 256>>>(ph, NN, 96, sA, sB, sD, sE);
        edge_kernel<<<EE / 128, 128, EDGE_SMEM>>>(C_w + l * 9216, C_b + l * 96,
                                                  src, dst);
        node_update_kernel<<<(NN * NDIM + 1023) / 1024, 1024>>>();
    }

    readout_kernel<<<nblk, 256>>>(m0w, m0b, m1w, m1b, m2w, m2b, out);
}

// round 9
// speedup vs baseline: 1.0104x; 1.0104x over previous
#include <cuda_runtime.h>

// GatedGCN: 4 layers of  e' = e + relu(Dh[src]+Eh[dst]+Ce);
//                        h' = h + relu(Ah + segsum(Bh[src]*sig(e'))/ (segsum(sig)+eps))
// followed by a 96->48->24->10 MLP + sigmoid.
// All GEMMs use packed fp32x2 FFMA (fma.rn.f32x2). The big per-edge GEMM
// (Ce = e @ Cw) is fused with the gating / atomic aggregation / e-residual.

#define NN   50000
#define EE   800000
#define NDIM 96
#define NCLS 10
#define EPSI 1e-6f

typedef unsigned long long u64;

// persistent device scratch (zero-init at module load; num/den invariantly
// zero at kernel_launch entry and re-zeroed defensively each call)
__device__ float g_h[NN * NDIM];
__device__ float g_e[(size_t)EE * NDIM];
__device__ float g_nbuf[4ull * NN * NDIM];   // slices: 0=Ah 1=Bh 2=Dh 3=Eh
__device__ float g_num[NN * NDIM];
__device__ float g_den[NN * NDIM];

__device__ __forceinline__ u64 pk2(float lo, float hi) {
    u64 r; asm("mov.b64 %0, {%1, %2};" : "=l"(r) : "f"(lo), "f"(hi)); return r;
}
__device__ __forceinline__ void upk2(u64 v, float& lo, float& hi) {
    asm("mov.b64 {%0, %1}, %2;" : "=f"(lo), "=f"(hi) : "l"(v));
}
__device__ __forceinline__ u64 ffma2(u64 a, u64 b, u64 c) {
    u64 d; asm("fma.rn.f32x2 %0, %1, %2, %3;" : "=l"(d) : "l"(a), "l"(b), "l"(c));
    return d;
}
__device__ __forceinline__ float sigmoidf_(float x) {
    return __fdividef(1.f, 1.f + __expf(-x));
}

// ---------------------------------------------------------------------------
// Generic [M,K] x [K,96] + b GEMM, K in {32,96}. blockIdx.y selects one of up
// to four (w,b,out) triples so all 4 node GEMMs of a layer run in one launch.
// Tile: 64 rows x 96 cols per block, 256 threads (16x16), thread tile 4x6
// (3 f32x2 column pairs), K chunked by 32 through SMEM.
// ---------------------------------------------------------------------------
struct GemmSet { const float* w; const float* b; float* out; };

__global__ __launch_bounds__(256) void gemm96_kernel(
        const float* __restrict__ x, int M, int K,
        GemmSet s0, GemmSet s1, GemmSet s2, GemmSet s3) {
    __shared__ __align__(16) float hs[64 * 97];
    __shared__ __align__(16) float ws[32 * 96];
    __shared__ float bs[96];
    const GemmSet s = (blockIdx.y == 0) ? s0 : (blockIdx.y == 1) ? s1
                    : (blockIdx.y == 2) ? s2 : s3;
    const int tid = threadIdx.x;
    const int tx = tid & 15, ty = tid >> 4;
    const int r0 = blockIdx.x * 64;

    for (int idx = tid; idx < 64 * K; idx += 256) {
        int r = idx / K, k = idx - r * K;
        int row = r0 + r;
        hs[r * 97 + k] = (row < M) ? x[row * K + k] : 0.f;
    }
    if (tid < 96) bs[tid] = s.b[tid];

    u64 acc[4][3];
#pragma unroll
    for (int i = 0; i < 4; ++i)
#pragma unroll
        for (int j = 0; j < 3; ++j) acc[i][j] = 0ull;

    const int nchunk = K >> 5;
    for (int c = 0; c < nchunk; ++c) {
        for (int idx = tid; idx < 32 * 96; idx += 256)
            ws[idx] = s.w[c * (32 * 96) + idx];
        __syncthreads();
#pragma unroll 8
        for (int kk = 0; kk < 32; ++kk) {
            u64 wp0 = *(const u64*)&ws[kk * 96 + tx * 6];
            u64 wp1 = *(const u64*)&ws[kk * 96 + tx * 6 + 2];
            u64 wp2 = *(const u64*)&ws[kk * 96 + tx * 6 + 4];
#pragma unroll
            for (int i = 0; i < 4; ++i) {
                float hv = hs[(ty + 16 * i) * 97 + (c << 5) + kk];
                u64 hh = pk2(hv, hv);
                acc[i][0] = ffma2(hh, wp0, acc[i][0]);
                acc[i][1] = ffma2(hh, wp1, acc[i][1]);
                acc[i][2] = ffma2(hh, wp2, acc[i][2]);
            }
        }
        __syncthreads();
    }

#pragma unroll
    for (int i = 0; i < 4; ++i) {
        int row = r0 + ty + 16 * i;
        if (row < M) {
#pragma unroll
            for (int j = 0; j < 3; ++j) {
                int col = tx * 6 + 2 * j;
                float lo, hi; upk2(acc[i][j], lo, hi);
                float2 o; o.x = lo + bs[col]; o.y = hi + bs[col + 1];
                *(float2*)&s.out[row * 96 + col] = o;
            }
        }
    }
}

// ---------------------------------------------------------------------------
// Fused edge kernel: per block of 128 edges
//   Ce = e_tile @ Cw        (register-tiled f32x2 GEMM, e transposed in SMEM)
//   e_new = Ce + Cb + Dh[src] + Eh[dst];  sigma = sigmoid(e_new)
//   atomic num[dst] += Bh[src]*sigma;  den[dst] += sigma
//   e <- e + relu(e_new)    (in place)
// 128 threads (8 tx x 16 ty): thread tile 8 rows x 6 f32x2 col-pairs.
// ---------------------------------------------------------------------------
#define EDGE_SMEM ((96 * 128 + 96 * 96 + 96) * 4 + 2 * 128 * 4)

__global__ __launch_bounds__(128) void edge_kernel(
        const float* __restrict__ Cw, const float* __restrict__ Cb,
        const int* __restrict__ src, const int* __restrict__ dst) {
    extern __shared__ __align__(16) float sm[];
    float* esT  = sm;                    // [96][128]  (k-major, conflict-free)
    float* ws   = sm + 96 * 128;         // [96][96]
    float* cbs  = ws + 96 * 96;          // [96]
    int*   ssrc = (int*)(cbs + 96);      // [128]
    int*   sdst = ssrc + 128;            // [128]

    const int tid = threadIdx.x;
    const int tx = tid & 7, ty = tid >> 3;
    const int e0 = blockIdx.x * 128;
    const int gbase = e0 * 96;

    for (int idx = tid; idx < 128 * 96; idx += 128) {
        int r = idx / 96, k = idx - r * 96;
        esT[k * 128 + r] = g_e[gbase + idx];
    }
    for (int idx = tid; idx < 96 * 96; idx += 128) ws[idx] = Cw[idx];
    if (tid < 96) cbs[tid] = Cb[tid];
    ssrc[tid] = src[e0 + tid];
    sdst[tid] = dst[e0 + tid];
    __syncthreads();

    u64 acc[8][6];
#pragma unroll
    for (int i = 0; i < 8; ++i)
#pragma unroll
        for (int j = 0; j < 6; ++j) acc[i][j] = 0ull;

#pragma unroll 4
    for (int k = 0; k < 96; ++k) {
        u64 wp[6];
#pragma unroll
        for (int j = 0; j < 6; ++j)
            wp[j] = *(const u64*)&ws[k * 96 + tx * 12 + 2 * j];
#pragma unroll
        for (int i = 0; i < 8; ++i) {
            float hv = esT[k * 128 + ty + 16 * i];
            u64 hh = pk2(hv, hv);
#pragma unroll
            for (int j = 0; j < 6; ++j) acc[i][j] = ffma2(hh, wp[j], acc[i][j]);
        }
    }

    const float* __restrict__ Bh = g_nbuf + 1ull * NN * 96;
    const float* __restrict__ Dh = g_nbuf + 2ull * NN * 96;
    const float* __restrict__ Eh = g_nbuf + 3ull * NN * 96;

#pragma unroll
    for (int i = 0; i < 8; ++i) {
        int r = ty + 16 * i;
        int s = ssrc[r] * 96;
        int d = sdst[r] * 96;
        int ebase = (e0 + r) * 96;
#pragma unroll
        for (int j = 0; j < 6; ++j) {
            int col = tx * 12 + 2 * j;
            float lo, hi; upk2(acc[i][j], lo, hi);
            float2 dh = *(const float2*)&Dh[s + col];
            float2 eh = *(const float2*)&Eh[d + col];
            float2 bh = *(const float2*)&Bh[s + col];
            float en0 = lo + cbs[col]     + dh.x + eh.x;
            float en1 = hi + cbs[col + 1] + dh.y + eh.y;
            float sg0 = sigmoidf_(en0);
            float sg1 = sigmoidf_(en1);
            atomicAdd(&g_num[d + col],     bh.x * sg0);
            atomicAdd(&g_num[d + col + 1], bh.y * sg1);
            atomicAdd(&g_den[d + col],     sg0);
            atomicAdd(&g_den[d + col + 1], sg1);
            float2 eo;
            eo.x = esT[col * 128 + r]       + fmaxf(en0, 0.f);
            eo.y = esT[(col + 1) * 128 + r] + fmaxf(en1, 0.f);
            *(float2*)&g_e[ebase + col] = eo;
        }
    }
}

// h <- h + relu(Ah + num/(den+eps));  reset num/den for the next layer/replay
__global__ void node_update_kernel() {
    int i = blockIdx.x * blockDim.x + threadIdx.x;
    if (i < NN * NDIM) {
        float hn = g_nbuf[i] + __fdividef(g_num[i], g_den[i] + EPSI);
        g_h[i] += fmaxf(hn, 0.f);
        g_num[i] = 0.f;
        g_den[i] = 0.f;
    }
}

__global__ void zero_nd_kernel() {
    int i = blockIdx.x * blockDim.x + threadIdx.x;
    if (i < NN * NDIM) { g_num[i] = 0.f; g_den[i] = 0.f; }
}

// ---------------------------------------------------------------------------
// Fused MLP readout + sigmoid: 64 nodes per block, all weights + activations
// staged in SMEM (odd-padded rows -> conflict-free).
// ---------------------------------------------------------------------------
__global__ __launch_bounds__(256) void readout_kernel(
        const float* __restrict__ w0, const float* __restrict__ b0,
        const float* __restrict__ w1, const float* __restrict__ b1,
        const float* __restrict__ w2, const float* __restrict__ b2,
        float* __restrict__ out) {
    __shared__ float w0s[96 * 48];
    __shared__ float w1s[48 * 24];
    __shared__ float w2s[24 * 10];
    __shared__ float b0s[48], b1s[24], b2s[10];
    __shared__ float y0s[64 * 49];
    __shared__ float y1s[64 * 25];

    const int tid = threadIdx.x;
    const int n0 = blockIdx.x * 64;

    for (int idx = tid; idx < 96 * 48; idx += 256) w0s[idx] = w0[idx];
    for (int idx = tid; idx < 48 * 24; idx += 256) w1s[idx] = w1[idx];
    if (tid < 24 * 10) w2s[tid] = w2[tid];
    if (tid < 48) b0s[tid] = b0[tid];
    if (tid < 24) b1s[tid] = b1[tid];
    if (tid < 10) b2s[tid] = b2[tid];
    __syncthreads();

    {   // layer 0: 96 -> 48, relu
        int n = tid & 63, cg = tid >> 6;       // 4 col groups of 12
        int row = n0 + n;
        float a[12];
#pragma unroll
        for (int c = 0; c < 12; ++c) a[c] = b0s[cg * 12 + c];
        if (row < NN) {
            for (int k = 0; k < 96; ++k) {
                float hv = g_h[row * 96 + k];
#pragma unroll
                for (int c = 0; c < 12; ++c) a[c] += hv * w0s[k * 48 + cg * 12 + c];
            }
        }
#pragma unroll
        for (int c = 0; c < 12; ++c) y0s[n * 49 + cg * 12 + c] = fmaxf(a[c], 0.f);
    }
    __syncthreads();
    {   // layer 1: 48 -> 24, relu
        int n = tid & 63, cg = tid >> 6;       // 4 col groups of 6
        float a[6];
#pragma unroll
        for (int c = 0; c < 6; ++c) a[c] = b1s[cg * 6 + c];
        for (int k = 0; k < 48; ++k) {
            float v = y0s[n * 49 + k];
#pragma unroll
            for (int c = 0; c < 6; ++c) a[c] += v * w1s[k * 24 + cg * 6 + c];
        }
#pragma unroll
        for (int c = 0; c < 6; ++c) y1s[n * 25 + cg * 6 + c] = fmaxf(a[c], 0.f);
    }
    __syncthreads();
    // layer 2: 24 -> 10, sigmoid
    for (int idx = tid; idx < 64 * NCLS; idx += 256) {
        int n = idx / NCLS, c = idx - n * NCLS;
        int row = n0 + n;
        if (row < NN) {
            float a = b2s[c];
#pragma unroll
            for (int k = 0; k < 24; ++k) a += y1s[n * 25 + k] * w2s[k * NCLS + c];
            out[row * NCLS + c] = sigmoidf_(a);
        }
    }
}

// ---------------------------------------------------------------------------
extern "C" void kernel_launch(void* const* d_in, const int* in_sizes, int n_in,
                              void* d_out, int out_size) {
    const float* h_in = (const float*)d_in[0];
    const float* e_in = (const float*)d_in[1];
    const int*   src  = (const int*)d_in[2];
    const int*   dst  = (const int*)d_in[3];
    const float* fp_w = (const float*)d_in[4];
    const float* fp_b = (const float*)d_in[5];
    const float* ep_w = (const float*)d_in[6];
    const float* ep_b = (const float*)d_in[7];
    const float* A_w  = (const float*)d_in[8];
    const float* A_b  = (const float*)d_in[9];
    const float* B_w  = (const float*)d_in[10];
    const float* B_b  = (const float*)d_in[11];
    const float* C_w  = (const float*)d_in[12];
    const float* C_b  = (const float*)d_in[13];
    const float* D_w  = (const float*)d_in[14];
    const float* D_b  = (const float*)d_in[15];
    const float* E_w  = (const float*)d_in[16];
    const float* E_b  = (const float*)d_in[17];
    const float* m0w  = (const float*)d_in[18];
    const float* m0b  = (const float*)d_in[19];
    const float* m1w  = (const float*)d_in[20];
    const float* m1b  = (const float*)d_in[21];
    const float* m2w  = (const float*)d_in[22];
    const float* m2b  = (const float*)d_in[23];
    float* out = (float*)d_out;

    float *ph, *pe, *pnb;
    cudaGetSymbolAddress((void**)&ph,  g_h);
    cudaGetSymbolAddress((void**)&pe,  g_e);
    cudaGetSymbolAddress((void**)&pnb, g_nbuf);

    cudaFuncSetAttribute(edge_kernel,
                         cudaFuncAttributeMaxDynamicSharedMemorySize, EDGE_SMEM);

    const int nblk = (NN + 63) / 64;            // 782
    zero_nd_kernel<<<(NN * NDIM + 1023) / 1024, 1024>>>();

    GemmSet sfp{fp_w, fp_b, ph};
    gemm96_kernel<<<dim3(nblk, 1), 256>>>(h_in, NN, 32, sfp, sfp, sfp, sfp);
    GemmSet sep{ep_w, ep_b, pe};
    gemm96_kernel<<<dim3(EE / 64, 1), 256>>>(e_in, EE, 32, sep, sep, sep, sep);

    for (int l = 0; l < 4; ++l) {
        GemmSet sA{A_w + l * 9216, A_b + l * 96, pnb};
        GemmSet sB{B_w + l * 9216, B_b + l * 96, pnb + 1ull * NN * 96};
        GemmSet sD{D_w + l * 9216, D_b + l * 96, pnb + 2ull * NN * 96};
        GemmSet sE{E_w + l * 9216, E_b + l * 96, pnb + 3ull * NN * 96};
        gemm96_kernel<<<dim3(nblk, 4), 256>>>(ph, NN, 96, sA, sB, sD, sE);
        edge_kernel<<<EE / 128, 128, EDGE_SMEM>>>(C_w + l * 9216, C_b + l * 96,
                                                  src, dst);
        node_update_kernel<<<(NN * NDIM + 1023) / 1024, 1024>>>();
    }

    readout_kernel<<<nblk, 256>>>(m0w, m0b, m1w, m1b, m2w, m2b, out);
}